// round 3
// baseline (speedup 1.0000x reference)
#include <cuda_runtime.h>
#include <cstdint>
#include <math.h>

#define BATCH 8
#define CDIM 192
#define C3 576
#define HEADS 8
#define CH 24
#define HH 128
#define WW 128
#define HW 16384
#define SPLIT 8

// ---------------- scratch (static device globals; no allocations) ----------------
__device__ float g_qkv[BATCH * C3 * HW];            // 301 MB
__device__ float g_qkvd[BATCH * C3 * HW];           // 301 MB
__device__ float g_var[BATCH * CDIM];
__device__ float g_nrmsq[BATCH * C3];
__device__ float g_attn_part[BATCH * HEADS * SPLIT * CH * CH];
__device__ float g_attn[BATCH * HEADS * CH * CH];
__device__ float g_W2[BATCH * CDIM * CDIM];

// ---------------- f32x2 helpers (FFMA2 path, full fp32 precision) ----------------
__device__ __forceinline__ unsigned long long pack2(float a) {
    unsigned long long r;
    unsigned int u = __float_as_uint(a);
    asm("mov.b64 %0, {%1, %1};" : "=l"(r) : "r"(u));
    return r;
}
__device__ __forceinline__ unsigned long long ffma2(unsigned long long a,
                                                    unsigned long long b,
                                                    unsigned long long c) {
    unsigned long long d;
    asm("fma.rn.f32x2 %0, %1, %2, %3;" : "=l"(d) : "l"(a), "l"(b), "l"(c));
    return d;
}
__device__ __forceinline__ float ull_lo(unsigned long long v) {
    return __uint_as_float((unsigned int)(v & 0xffffffffull));
}
__device__ __forceinline__ float ull_hi(unsigned long long v) {
    return __uint_as_float((unsigned int)(v >> 32));
}

// ---------------- K1: depthwise 3x3 on x + unbiased variance over HW ----------------
__global__ void k_var(const float* __restrict__ x, const float* __restrict__ w_dw) {
    int bc = blockIdx.x;                       // b*192 + c
    const float* in = x + (size_t)bc * HW;
    const float* wp = w_dw + (bc % CDIM) * 9;
    float wv[9];
#pragma unroll
    for (int i = 0; i < 9; i++) wv[i] = wp[i];

    float s1 = 0.f, s2 = 0.f;
    for (int idx = threadIdx.x; idx < HW; idx += blockDim.x) {
        int y = idx >> 7, xx = idx & 127;
        float a = 0.f;
#pragma unroll
        for (int dy = 0; dy < 3; dy++) {
            int yy = y + dy - 1;
            if (yy < 0 || yy > 127) continue;
            const float* row = in + yy * WW;
#pragma unroll
            for (int dx = 0; dx < 3; dx++) {
                int xc = xx + dx - 1;
                if (xc < 0 || xc > 127) continue;
                a += wv[dy * 3 + dx] * row[xc];
            }
        }
        s1 += a;
        s2 += a * a;
    }
#pragma unroll
    for (int o = 16; o; o >>= 1) {
        s1 += __shfl_xor_sync(0xffffffffu, s1, o);
        s2 += __shfl_xor_sync(0xffffffffu, s2, o);
    }
    __shared__ float r1[8], r2[8];
    if ((threadIdx.x & 31) == 0) { r1[threadIdx.x >> 5] = s1; r2[threadIdx.x >> 5] = s2; }
    __syncthreads();
    if (threadIdx.x == 0) {
        float t1 = 0.f, t2 = 0.f;
#pragma unroll
        for (int i = 0; i < 8; i++) { t1 += r1[i]; t2 += r2[i]; }
        g_var[bc] = (t2 - t1 * t1 * (1.0f / 16384.0f)) * (1.0f / 16383.0f);
    }
}

// ---------------- K3: depthwise 3x3 on qkv + sum-of-squares (q,k norms) ----------------
__global__ void k_dw(const float* __restrict__ w_qkvdw) {
    int p = blockIdx.x;                        // b*576 + ch
    int ch = p % C3;
    const float* in = g_qkv + (size_t)p * HW;
    float* out = g_qkvd + (size_t)p * HW;
    const float* wp = w_qkvdw + ch * 9;
    float wv[9];
#pragma unroll
    for (int i = 0; i < 9; i++) wv[i] = wp[i];

    float ss = 0.f;
    for (int idx = threadIdx.x; idx < HW; idx += blockDim.x) {
        int y = idx >> 7, xx = idx & 127;
        float a = 0.f;
#pragma unroll
        for (int dy = 0; dy < 3; dy++) {
            int yy = y + dy - 1;
            if (yy < 0 || yy > 127) continue;
            const float* row = in + yy * WW;
#pragma unroll
            for (int dx = 0; dx < 3; dx++) {
                int xc = xx + dx - 1;
                if (xc < 0 || xc > 127) continue;
                a += wv[dy * 3 + dx] * row[xc];
            }
        }
        out[idx] = a;
        ss += a * a;
    }
#pragma unroll
    for (int o = 16; o; o >>= 1) ss += __shfl_xor_sync(0xffffffffu, ss, o);
    __shared__ float rr[8];
    if ((threadIdx.x & 31) == 0) rr[threadIdx.x >> 5] = ss;
    __syncthreads();
    if (threadIdx.x == 0) {
        float t = 0.f;
#pragma unroll
        for (int i = 0; i < 8; i++) t += rr[i];
        g_nrmsq[p] = t;
    }
}

// ---------------- SGEMM (f32x2): C[z] = A[z](MxK) * B[z](KxN), row-major ----------------
#define GBM 64
#define GBN 256
#define GBK 16
__global__ __launch_bounds__(256) void k_gemm(const float* __restrict__ A,
                                              const float* __restrict__ B,
                                              float* __restrict__ C,
                                              int N, int K,
                                              long long sA, long long sB, long long sC) {
    __shared__ float As[GBK][GBM + 1];
    __shared__ float Bs[GBK][GBN];

    const float* Ab = A + (size_t)blockIdx.z * sA;
    const float* Bb = B + (size_t)blockIdx.z * sB;
    float* Cb = C + (size_t)blockIdx.z * sC;

    int m0 = blockIdx.y * GBM;
    int n0 = blockIdx.x * GBN;
    int tid = threadIdx.x;
    int tm = tid >> 5;          // 0..7  -> 8 rows each
    int tn = tid & 31;          // 0..31 -> 8 cols each

    unsigned long long acc[8][4];
#pragma unroll
    for (int i = 0; i < 8; i++)
#pragma unroll
        for (int j = 0; j < 4; j++) acc[i][j] = 0ull;

    for (int kk = 0; kk < K; kk += GBK) {
        // load A tile (64x16) transposed into As[k][m]
#pragma unroll
        for (int t = 0; t < (GBM * GBK) / 256; t++) {
            int i = tid + t * 256;
            int r = i >> 4, c = i & 15;
            As[c][r] = Ab[(size_t)(m0 + r) * K + kk + c];
        }
        // load B tile (16x256) via float4
#pragma unroll
        for (int t = 0; t < (GBK * GBN) / (256 * 4); t++) {
            int s = tid + t * 256;
            int r = s >> 6, c4 = s & 63;
            *(float4*)&Bs[r][c4 * 4] =
                *(const float4*)&Bb[(size_t)(kk + r) * N + n0 + c4 * 4];
        }
        __syncthreads();
#pragma unroll
        for (int k = 0; k < GBK; k++) {
            unsigned long long ap[8];
#pragma unroll
            for (int i = 0; i < 8; i++) ap[i] = pack2(As[k][tm * 8 + i]);
            ulonglong2 bb0 = *reinterpret_cast<const ulonglong2*>(&Bs[k][tn * 8]);
            ulonglong2 bb1 = *reinterpret_cast<const ulonglong2*>(&Bs[k][tn * 8 + 4]);
            unsigned long long bp[4] = {bb0.x, bb0.y, bb1.x, bb1.y};
#pragma unroll
            for (int i = 0; i < 8; i++)
#pragma unroll
                for (int j = 0; j < 4; j++) acc[i][j] = ffma2(ap[i], bp[j], acc[i][j]);
        }
        __syncthreads();
    }
#pragma unroll
    for (int i = 0; i < 8; i++) {
        float* crow = Cb + (size_t)(m0 + tm * 8 + i) * N + n0 + tn * 8;
        float4 o;
        o.x = ull_lo(acc[i][0]); o.y = ull_hi(acc[i][0]);
        o.z = ull_lo(acc[i][1]); o.w = ull_hi(acc[i][1]);
        *(float4*)crow = o;
        o.x = ull_lo(acc[i][2]); o.y = ull_hi(acc[i][2]);
        o.z = ull_lo(acc[i][3]); o.w = ull_hi(acc[i][3]);
        *(float4*)(crow + 4) = o;
    }
}

// ---------------- K4: attn partial sums q·k^T over n-chunks ----------------
__global__ __launch_bounds__(256) void k_attn_part() {
    __shared__ float Qs[CH][64];
    __shared__ float Ks[CH][64];
    int bh = blockIdx.x / SPLIT, sp = blockIdx.x % SPLIT;
    int b = bh >> 3, h = bh & 7;
    const float* qb = g_qkvd + ((size_t)b * C3 + h * CH) * HW;
    const float* kb = g_qkvd + ((size_t)b * C3 + CDIM + h * CH) * HW;
    int tid = threadIdx.x, lane = tid & 31, wrp = tid >> 5;  // wrp 0..7

    float acc[3][CH];
#pragma unroll
    for (int r = 0; r < 3; r++)
#pragma unroll
        for (int d = 0; d < CH; d++) acc[r][d] = 0.f;

    int n_start = sp * (HW / SPLIT);
    for (int n0 = n_start; n0 < n_start + HW / SPLIT; n0 += 64) {
        for (int i = tid; i < CH * 64; i += 256) {
            int r = i >> 6, c = i & 63;
            Qs[r][c] = qb[(size_t)r * HW + n0 + c];
            Ks[r][c] = kb[(size_t)r * HW + n0 + c];
        }
        __syncthreads();
#pragma unroll
        for (int rep = 0; rep < 2; rep++) {
            int ii = lane + rep * 32;
            float q0 = Qs[wrp][ii], q1 = Qs[wrp + 8][ii], q2 = Qs[wrp + 16][ii];
#pragma unroll
            for (int d = 0; d < CH; d++) {
                float kkv = Ks[d][ii];
                acc[0][d] += q0 * kkv;
                acc[1][d] += q1 * kkv;
                acc[2][d] += q2 * kkv;
            }
        }
        __syncthreads();
    }
#pragma unroll
    for (int r = 0; r < 3; r++)
#pragma unroll
        for (int d = 0; d < CH; d++)
#pragma unroll
            for (int o = 16; o; o >>= 1)
                acc[r][d] += __shfl_down_sync(0xffffffffu, acc[r][d], o);
    if (lane == 0) {
        size_t base = (size_t)blockIdx.x * (CH * CH);
#pragma unroll
        for (int r = 0; r < 3; r++) {
            int c = wrp + r * 8;
            for (int d = 0; d < CH; d++) g_attn_part[base + c * CH + d] = acc[r][d];
        }
    }
}

// ---------------- K5: finalize attention (norms, temperature, diag, softmax) ----------------
__global__ void k_attn_fin(const float* __restrict__ temperature,
                           const float* __restrict__ rescale) {
    int bh = blockIdx.x;
    int b = bh >> 3, h = bh & 7;
    int c = threadIdx.x >> 5;     // 24 warps: row c
    int lane = threadIdx.x & 31;  // d in lanes 0..23
    float val;
    if (lane < CH) {
        int d = lane;
        float raw = 0.f;
#pragma unroll
        for (int s = 0; s < SPLIT; s++)
            raw += g_attn_part[(size_t)(bh * SPLIT + s) * (CH * CH) + c * CH + d];
        float nq = sqrtf(g_nrmsq[b * C3 + h * CH + c]);
        float nk = sqrtf(g_nrmsq[b * C3 + CDIM + h * CH + d]);
        val = raw / (fmaxf(nq, 1e-12f) * fmaxf(nk, 1e-12f)) * temperature[h];
        if (c == d) val += rescale[h] * g_var[b * CDIM + h * CH + c];
    } else {
        val = -INFINITY;
    }
    float mx = val;
#pragma unroll
    for (int o = 16; o; o >>= 1) mx = fmaxf(mx, __shfl_xor_sync(0xffffffffu, mx, o));
    float ex = (lane < CH) ? expf(val - mx) : 0.f;
    float sm = ex;
#pragma unroll
    for (int o = 16; o; o >>= 1) sm += __shfl_xor_sync(0xffffffffu, sm, o);
    if (lane < CH) g_attn[(size_t)bh * (CH * CH) + c * CH + lane] = ex / sm;
}

// ---------------- K6: W2[b] = w_proj @ blockdiag(attn[b]) ----------------
__global__ void k_w2(const float* __restrict__ w_proj) {
    int bh = blockIdx.x;
    int b = bh >> 3, h = bh & 7;
    int co = threadIdx.x;  // 0..191
    __shared__ float at[CH][CH];
    for (int i = co; i < CH * CH; i += CDIM)
        at[i / CH][i % CH] = g_attn[(size_t)bh * (CH * CH) + i];
    __syncthreads();
    float wpv[CH];
#pragma unroll
    for (int cc = 0; cc < CH; cc++) wpv[cc] = w_proj[co * CDIM + h * CH + cc];
#pragma unroll
    for (int d = 0; d < CH; d++) {
        float a = 0.f;
#pragma unroll
        for (int cc = 0; cc < CH; cc++) a += wpv[cc] * at[cc][d];
        g_W2[((size_t)b * CDIM + co) * CDIM + h * CH + d] = a;
    }
}

// ---------------- launch ----------------
extern "C" void kernel_launch(void* const* d_in, const int* in_sizes, int n_in,
                              void* d_out, int out_size) {
    const float* x           = (const float*)d_in[0];
    const float* w_dw        = (const float*)d_in[1];
    const float* w_qkv       = (const float*)d_in[2];
    const float* w_qkvdw     = (const float*)d_in[3];
    const float* w_proj      = (const float*)d_in[4];
    const float* temperature = (const float*)d_in[5];
    const float* rescale     = (const float*)d_in[6];
    float* out = (float*)d_out;

    float *p_qkv, *p_qkvd, *p_W2;
    cudaGetSymbolAddress((void**)&p_qkv, g_qkv);
    cudaGetSymbolAddress((void**)&p_qkvd, g_qkvd);
    cudaGetSymbolAddress((void**)&p_W2, g_W2);

    // 1. variance of depthwise(x)
    k_var<<<BATCH * CDIM, 256>>>(x, w_dw);
    // 2. qkv = w_qkv @ x  (per-batch GEMM 576 x 16384 x 192)
    k_gemm<<<dim3(HW / GBN, C3 / GBM, BATCH), 256>>>(
        w_qkv, x, p_qkv, HW, CDIM,
        0LL, (long long)CDIM * HW, (long long)C3 * HW);
    // 3. depthwise on qkv + q/k sum-of-squares
    k_dw<<<BATCH * C3, 256>>>(w_qkvdw);
    // 4. attention partial dots
    k_attn_part<<<BATCH * HEADS * SPLIT, 256>>>();
    // 5. softmax finalize
    k_attn_fin<<<BATCH * HEADS, CH * 32>>>(temperature, rescale);
    // 6. fold proj into attn
    k_w2<<<BATCH * HEADS, CDIM>>>(w_proj);
    // 7. out = W2 @ v  (per-batch GEMM 192 x 16384 x 192), writes d_out
    k_gemm<<<dim3(HW / GBN, CDIM / GBM, BATCH), 256>>>(
        p_W2, p_qkvd + (size_t)2 * CDIM * HW, out, HW, CDIM,
        (long long)CDIM * CDIM, (long long)C3 * HW, (long long)CDIM * HW);
}

// round 6
// speedup vs baseline: 1.4527x; 1.4527x over previous
#include <cuda_runtime.h>
#include <cuda_bf16.h>
#include <cstdint>
#include <math.h>

#define BATCH 8
#define CDIM 192
#define C3 576
#define HEADS 8
#define CH 24
#define HW 16384
#define KTOT 576          // split-K: [hi | lo | hi] x [hi | hi | lo] pairing
#define RBQK 32           // rowblocks (4 rows each) in fused qk kernel

// ---------------- scratch (static device globals; zero-initialized) ----------------
__device__ float g_qkv[BATCH * C3 * HW];                    // fp32 qkv (301 MB)
__device__ __nv_bfloat16 g_B1[(size_t)BATCH * HW * KTOT];   // x split/transposed (151 MB)
__device__ __nv_bfloat16 g_V[(size_t)BATCH * HW * KTOT];    // v dw split/transposed (151 MB)
__device__ __nv_bfloat16 g_A1[640 * KTOT];                  // w_qkv split (rows 576..639 stay 0)
__device__ __nv_bfloat16 g_A2[BATCH * 256 * KTOT];          // W2 split (rows 192..255 stay 0)
__device__ float g_var[BATCH * CDIM];
__device__ float g_attn_part[BATCH * HEADS * RBQK * CH * CH];
__device__ float g_nrm_part[BATCH * HEADS * RBQK * 48];
__device__ float g_attn[BATCH * HEADS * CH * CH];

// ---------------- helpers ----------------
__device__ __forceinline__ uint32_t smem_u32(const void* p) {
    uint32_t a;
    asm("{ .reg .u64 t; cvta.to.shared.u64 t, %1; cvt.u32.u64 %0, t; }" : "=r"(a) : "l"(p));
    return a;
}
#define CP_ASYNC16(s, g) \
    asm volatile("cp.async.cg.shared.global [%0], [%1], 16;" :: "r"(s), "l"(g) : "memory")
#define CP_COMMIT asm volatile("cp.async.commit_group;" ::: "memory")
#define CP_WAIT0 asm volatile("cp.async.wait_group 0;" ::: "memory")

__device__ __forceinline__ void ldm_x4(uint32_t* d, uint32_t addr) {
    asm volatile("ldmatrix.sync.aligned.m8n8.x4.shared.b16 {%0,%1,%2,%3}, [%4];"
                 : "=r"(d[0]), "=r"(d[1]), "=r"(d[2]), "=r"(d[3]) : "r"(addr));
}
__device__ __forceinline__ void mma16816(float* c, const uint32_t* a, uint32_t b0, uint32_t b1) {
    asm volatile(
        "mma.sync.aligned.m16n8k16.row.col.f32.bf16.bf16.f32 "
        "{%0,%1,%2,%3}, {%4,%5,%6,%7}, {%8,%9}, {%0,%1,%2,%3};"
        : "+f"(c[0]), "+f"(c[1]), "+f"(c[2]), "+f"(c[3])
        : "r"(a[0]), "r"(a[1]), "r"(a[2]), "r"(a[3]), "r"(b0), "r"(b1));
}

__device__ __forceinline__ uint32_t bfsplit_pack(float v) {
    __nv_bfloat16 hi = __float2bfloat16(v);
    __nv_bfloat16 lo = __float2bfloat16(v - __bfloat162float(hi));
    return (uint32_t)__bfloat16_as_ushort(hi) | ((uint32_t)__bfloat16_as_ushort(lo) << 16);
}

// ---------------- K1: depthwise 3x3 on x + unbiased variance over HW ----------------
__global__ void k_var(const float* __restrict__ x, const float* __restrict__ w_dw) {
    int bc = blockIdx.x;
    const float* in = x + (size_t)bc * HW;
    const float* wp = w_dw + (bc % CDIM) * 9;
    float wv[9];
#pragma unroll
    for (int i = 0; i < 9; i++) wv[i] = wp[i];
    float s1 = 0.f, s2 = 0.f;
    for (int idx = threadIdx.x; idx < HW; idx += blockDim.x) {
        int y = idx >> 7, xx = idx & 127;
        float a = 0.f;
#pragma unroll
        for (int dy = 0; dy < 3; dy++) {
            int yy = y + dy - 1;
            if (yy < 0 || yy > 127) continue;
            const float* row = in + yy * 128;
#pragma unroll
            for (int dx = 0; dx < 3; dx++) {
                int xc = xx + dx - 1;
                if (xc < 0 || xc > 127) continue;
                a += wv[dy * 3 + dx] * row[xc];
            }
        }
        s1 += a; s2 += a * a;
    }
#pragma unroll
    for (int o = 16; o; o >>= 1) {
        s1 += __shfl_xor_sync(0xffffffffu, s1, o);
        s2 += __shfl_xor_sync(0xffffffffu, s2, o);
    }
    __shared__ float r1[8], r2[8];
    if ((threadIdx.x & 31) == 0) { r1[threadIdx.x >> 5] = s1; r2[threadIdx.x >> 5] = s2; }
    __syncthreads();
    if (threadIdx.x == 0) {
        float t1 = 0.f, t2 = 0.f;
#pragma unroll
        for (int i = 0; i < 8; i++) { t1 += r1[i]; t2 += r2[i]; }
        g_var[bc] = (t2 - t1 * t1 * (1.0f / 16384.0f)) * (1.0f / 16383.0f);
    }
}

// ---------------- K2: split+transpose x -> g_B1[b][n][576] = [xh | xl | xh] ----------------
__global__ void k_splitB(const float* __restrict__ x) {
    extern __shared__ unsigned int sh[];   // [256][65]
    int nt = blockIdx.x, cg = blockIdx.y, b = blockIdx.z;
    int t = threadIdx.x;
    int n0 = nt * 256;
    const float* xb = x + ((size_t)b * CDIM + cg * 64) * HW + n0;
#pragma unroll 4
    for (int j = 0; j < 64; j++)
        sh[t * 65 + j] = bfsplit_pack(xb[(size_t)j * HW + t]);
    __syncthreads();
    __nv_bfloat16* Bb = g_B1 + (size_t)b * HW * KTOT;
    int lane = t & 31, w = t >> 5;
    for (int r = w; r < 256; r += 8) {
        unsigned int e0 = sh[r * 65 + lane * 2];
        unsigned int e1 = sh[r * 65 + lane * 2 + 1];
        unsigned int hi2 = (e0 & 0xFFFFu) | (e1 << 16);
        unsigned int lo2 = (e0 >> 16) | (e1 & 0xFFFF0000u);
        size_t rowb = (size_t)(n0 + r) * KTOT + cg * 64 + lane * 2;
        *(unsigned int*)(Bb + rowb) = hi2;
        *(unsigned int*)(Bb + rowb + 192) = lo2;
        *(unsigned int*)(Bb + rowb + 384) = hi2;
    }
}

// ---------------- K3: split w_qkv -> g_A1[m][576] = [Wh | Wh | Wl] ----------------
__global__ void k_prepA1(const float* __restrict__ w_qkv) {
    int m = blockIdx.x, c = threadIdx.x;
    unsigned int pk = bfsplit_pack(w_qkv[m * CDIM + c]);
    __nv_bfloat16 hi = __ushort_as_bfloat16((unsigned short)(pk & 0xFFFF));
    __nv_bfloat16 lo = __ushort_as_bfloat16((unsigned short)(pk >> 16));
    g_A1[m * KTOT + c] = hi;
    g_A1[m * KTOT + 192 + c] = hi;
    g_A1[m * KTOT + 384 + c] = lo;
}

// ---------------- K4: bf16 HMMA GEMM  C[128m x 128n] = A(MxK) · B(NxK)^T, K=576 ----------------
#define BM 128
#define BN 128
#define BK 32
#define KITERS (KTOT / BK)     // 18
#define SROW 40                // padded row stride (halves): 80B -> conflict-free ldmatrix

__global__ __launch_bounds__(256)
void k_gemm_mma(const __nv_bfloat16* __restrict__ A, const __nv_bfloat16* __restrict__ B,
                float* __restrict__ C, int M_valid,
                long long sA, long long sB, long long sC) {
    __shared__ __align__(16) __nv_bfloat16 As[2][BM][SROW];
    __shared__ __align__(16) __nv_bfloat16 Bs[2][BN][SROW];
    int tid = threadIdx.x, lane = tid & 31, wid = tid >> 5;
    int wm = wid & 1, wn = wid >> 1;          // warps: 2 (M) x 4 (N)
    int n0 = blockIdx.x * BN, m0 = blockIdx.y * BM, bz = blockIdx.z;
    const __nv_bfloat16* Ab = A + (size_t)bz * sA;
    const __nv_bfloat16* Bb = B + (size_t)bz * sB;
    float* Cb = C + (size_t)bz * sC;

    float acc[4][4][4];
#pragma unroll
    for (int im = 0; im < 4; im++)
#pragma unroll
        for (int in = 0; in < 4; in++)
#pragma unroll
            for (int q = 0; q < 4; q++) acc[im][in][q] = 0.f;

    // prefetch stage 0
    {
        int kk = 0;
#pragma unroll
        for (int p = 0; p < 2; p++) {
            int i = tid + p * 256;
            int r = i >> 2, cc = i & 3;
            CP_ASYNC16(smem_u32(&As[0][r][cc * 8]), Ab + (size_t)(m0 + r) * KTOT + kk + cc * 8);
            CP_ASYNC16(smem_u32(&Bs[0][r][cc * 8]), Bb + (size_t)(n0 + r) * KTOT + kk + cc * 8);
        }
        CP_COMMIT;
    }

    for (int it = 0; it < KITERS; it++) {
        CP_WAIT0;
        __syncthreads();
        if (it + 1 < KITERS) {
            int kk = (it + 1) * BK;
            int stg = (it + 1) & 1;
#pragma unroll
            for (int p = 0; p < 2; p++) {
                int i = tid + p * 256;
                int r = i >> 2, cc = i & 3;
                CP_ASYNC16(smem_u32(&As[stg][r][cc * 8]),
                           Ab + (size_t)(m0 + r) * KTOT + kk + cc * 8);
                CP_ASYNC16(smem_u32(&Bs[stg][r][cc * 8]),
                           Bb + (size_t)(n0 + r) * KTOT + kk + cc * 8);
            }
            CP_COMMIT;
        }
        int stg = it & 1;
#pragma unroll
        for (int ks = 0; ks < 2; ks++) {
            int k0 = ks * 16;
            uint32_t af[4][4];
#pragma unroll
            for (int im = 0; im < 4; im++) {
                uint32_t a = smem_u32(
                    &As[stg][wm * 64 + im * 16 + (lane & 15)][k0 + ((lane >> 4) << 3)]);
                ldm_x4(af[im], a);
            }
            uint32_t bf[2][4];
#pragma unroll
            for (int ip = 0; ip < 2; ip++) {
                // lanes 0-7:  rows n+0..7,  col k0      -> matrix0 (n0-7,  k0-7)
                // lanes 8-15: rows n+0..7,  col k0+8    -> matrix1 (n0-7,  k8-15)
                // lanes 16-23: rows n+8..15, col k0     -> matrix2 (n8-15, k0-7)
                // lanes 24-31: rows n+8..15, col k0+8   -> matrix3 (n8-15, k8-15)
                uint32_t a = smem_u32(
                    &Bs[stg][wn * 32 + ip * 16 + ((lane >> 4) << 3) + (lane & 7)]
                       [k0 + (lane & 8)]);
                ldm_x4(bf[ip], a);
            }
#pragma unroll
            for (int im = 0; im < 4; im++)
#pragma unroll
                for (int in = 0; in < 4; in++) {
                    int ip = in >> 1, sub = in & 1;
                    mma16816(acc[im][in], af[im], bf[ip][sub * 2], bf[ip][sub * 2 + 1]);
                }
        }
        __syncthreads();
    }

    // epilogue
    int g = lane >> 2, tg = lane & 3;
#pragma unroll
    for (int im = 0; im < 4; im++) {
#pragma unroll
        for (int rr = 0; rr < 2; rr++) {
            int m = m0 + wm * 64 + im * 16 + g + rr * 8;
            if (m < M_valid) {
                float* dst = Cb + (size_t)m * HW + n0 + wn * 32 + tg * 2;
#pragma unroll
                for (int in = 0; in < 4; in++) {
                    float2 v = make_float2(acc[im][in][rr * 2], acc[im][in][rr * 2 + 1]);
                    *(float2*)(dst + in * 8) = v;
                }
            }
        }
    }
}

// ---------------- K5: fused depthwise(q,k) + qk partial dots + norm partials ----------------
__global__ __launch_bounds__(256) void k_fused_qk(const float* __restrict__ w_qkvdw) {
    extern __shared__ float qkbuf[];        // Qd[24][512] Kd[24][512]
    float* Qd = qkbuf;
    float* Kd = qkbuf + 24 * 512;
    int rb = blockIdx.x, bh = blockIdx.y;
    int b = bh >> 3, h = bh & 7;
    int y0 = rb * 4;
    int tid = threadIdx.x;

    for (int j = 0; j < 48; j++) {
        int ch = (j < 24) ? h * 24 + j : 192 + h * 24 + (j - 24);
        const float* in = g_qkv + (((size_t)b * C3 + ch) << 14);
        const float* wp = w_qkvdw + ch * 9;
        float wv[9];
#pragma unroll
        for (int i = 0; i < 9; i++) wv[i] = wp[i];
        float* dst = (j < 24) ? (Qd + j * 512) : (Kd + (j - 24) * 512);
        for (int p = tid; p < 512; p += 256) {
            int y = y0 + (p >> 7), xx = p & 127;
            float a = 0.f;
#pragma unroll
            for (int dy = 0; dy < 3; dy++) {
                int yy = y + dy - 1;
                if (yy < 0 || yy > 127) continue;
                const float* row = in + yy * 128;
#pragma unroll
                for (int dx = 0; dx < 3; dx++) {
                    int xc = xx + dx - 1;
                    if (xc < 0 || xc > 127) continue;
                    a += wv[dy * 3 + dx] * row[xc];
                }
            }
            dst[p] = a;
        }
    }
    __syncthreads();

    int lane = tid & 31, w = tid >> 5;
    int c0 = w, c1 = w + 8, c2 = w + 16;
    float acc0[24], acc1[24], acc2[24];
#pragma unroll
    for (int d = 0; d < 24; d++) { acc0[d] = 0.f; acc1[d] = 0.f; acc2[d] = 0.f; }
    float qs0 = 0.f, qs1 = 0.f, qs2 = 0.f, ks0 = 0.f, ks1 = 0.f, ks2 = 0.f;
#pragma unroll 4
    for (int it = 0; it < 16; it++) {
        int ii = lane + it * 32;
        float q0 = Qd[c0 * 512 + ii], q1 = Qd[c1 * 512 + ii], q2 = Qd[c2 * 512 + ii];
        float k0 = Kd[c0 * 512 + ii], k1 = Kd[c1 * 512 + ii], k2 = Kd[c2 * 512 + ii];
        qs0 += q0 * q0; qs1 += q1 * q1; qs2 += q2 * q2;
        ks0 += k0 * k0; ks1 += k1 * k1; ks2 += k2 * k2;
#pragma unroll
        for (int d = 0; d < 24; d++) {
            float kv = Kd[d * 512 + ii];
            acc0[d] += q0 * kv; acc1[d] += q1 * kv; acc2[d] += q2 * kv;
        }
    }
#pragma unroll
    for (int o = 16; o; o >>= 1) {
#pragma unroll
        for (int d = 0; d < 24; d++) {
            acc0[d] += __shfl_down_sync(0xffffffffu, acc0[d], o);
            acc1[d] += __shfl_down_sync(0xffffffffu, acc1[d], o);
            acc2[d] += __shfl_down_sync(0xffffffffu, acc2[d], o);
        }
        qs0 += __shfl_down_sync(0xffffffffu, qs0, o);
        qs1 += __shfl_down_sync(0xffffffffu, qs1, o);
        qs2 += __shfl_down_sync(0xffffffffu, qs2, o);
        ks0 += __shfl_down_sync(0xffffffffu, ks0, o);
        ks1 += __shfl_down_sync(0xffffffffu, ks1, o);
        ks2 += __shfl_down_sync(0xffffffffu, ks2, o);
    }
    if (lane == 0) {
        float* ap = g_attn_part + ((size_t)bh * RBQK + rb) * 576;
        float* np = g_nrm_part + ((size_t)bh * RBQK + rb) * 48;
#pragma unroll
        for (int d = 0; d < 24; d++) {
            ap[c0 * 24 + d] = acc0[d];
            ap[c1 * 24 + d] = acc1[d];
            ap[c2 * 24 + d] = acc2[d];
        }
        np[c0] = qs0; np[c1] = qs1; np[c2] = qs2;
        np[24 + c0] = ks0; np[24 + c1] = ks1; np[24 + c2] = ks2;
    }
}

// ---------------- K6: depthwise(v) + split + transpose -> g_V[b][n][576] ----------------
__global__ void k_dwv(const float* __restrict__ w_qkvdw) {
    extern __shared__ unsigned int sh[];   // [256][65]
    int rp = blockIdx.x, cg = blockIdx.y, b = blockIdx.z;
    int t = threadIdx.x;
    int y0 = rp * 2;
    int y = y0 + (t >> 7), xx = t & 127;
    for (int j = 0; j < 64; j++) {
        int ch = 384 + cg * 64 + j;
        const float* in = g_qkv + (((size_t)b * C3 + ch) << 14);
        const float* wp = w_qkvdw + ch * 9;
        float wv[9];
#pragma unroll
        for (int i = 0; i < 9; i++) wv[i] = wp[i];
        float a = 0.f;
#pragma unroll
        for (int dy = 0; dy < 3; dy++) {
            int yy = y + dy - 1;
            if (yy < 0 || yy > 127) continue;
            const float* row = in + yy * 128;
#pragma unroll
            for (int dx = 0; dx < 3; dx++) {
                int xc = xx + dx - 1;
                if (xc < 0 || xc > 127) continue;
                a += wv[dy * 3 + dx] * row[xc];
            }
        }
        sh[t * 65 + j] = bfsplit_pack(a);
    }
    __syncthreads();
    __nv_bfloat16* Vb = g_V + (size_t)b * HW * KTOT;
    int lane = t & 31, w = t >> 5;
    int n0 = y0 * 128;
    for (int r = w; r < 256; r += 8) {
        unsigned int e0 = sh[r * 65 + lane * 2];
        unsigned int e1 = sh[r * 65 + lane * 2 + 1];
        unsigned int hi2 = (e0 & 0xFFFFu) | (e1 << 16);
        unsigned int lo2 = (e0 >> 16) | (e1 & 0xFFFF0000u);
        size_t rowb = (size_t)(n0 + r) * KTOT + cg * 64 + lane * 2;
        *(unsigned int*)(Vb + rowb) = hi2;
        *(unsigned int*)(Vb + rowb + 192) = lo2;
        *(unsigned int*)(Vb + rowb + 384) = hi2;
    }
}

// ---------------- K7: finalize attention (norms, temperature, diag, softmax) ----------------
__global__ void k_attn_fin(const float* __restrict__ temperature,
                           const float* __restrict__ rescale) {
    int bh = blockIdx.x;
    int b = bh >> 3, h = bh & 7;
    int c = threadIdx.x >> 5, lane = threadIdx.x & 31;
    float val;
    if (lane < 24) {
        float raw = 0.f, nq2 = 0.f, nk2 = 0.f;
        for (int s = 0; s < RBQK; s++) {
            const float* ap = g_attn_part + ((size_t)bh * RBQK + s) * 576;
            const float* np = g_nrm_part + ((size_t)bh * RBQK + s) * 48;
            raw += ap[c * 24 + lane];
            nq2 += np[c];
            nk2 += np[24 + lane];
        }
        float nq = sqrtf(nq2), nk = sqrtf(nk2);
        val = raw / (fmaxf(nq, 1e-12f) * fmaxf(nk, 1e-12f)) * temperature[h];
        if (c == lane) val += rescale[h] * g_var[b * CDIM + h * 24 + c];
    } else {
        val = -INFINITY;
    }
    float mx = val;
#pragma unroll
    for (int o = 16; o; o >>= 1) mx = fmaxf(mx, __shfl_xor_sync(0xffffffffu, mx, o));
    float ex = (lane < 24) ? expf(val - mx) : 0.f;
    float sm = ex;
#pragma unroll
    for (int o = 16; o; o >>= 1) sm += __shfl_xor_sync(0xffffffffu, sm, o);
    if (lane < 24) g_attn[(size_t)bh * 576 + c * 24 + lane] = ex / sm;
}

// ---------------- K8: W2 = w_proj @ blockdiag(attn) -> g_A2 split [Wh | Wh | Wl] ----------------
__global__ void k_w2(const float* __restrict__ w_proj) {
    int bh = blockIdx.x;
    int b = bh >> 3, h = bh & 7;
    int co = threadIdx.x;  // 0..191
    __shared__ float at[24][24];
    for (int i = co; i < 576; i += 192) at[i / 24][i % 24] = g_attn[(size_t)bh * 576 + i];
    __syncthreads();
    float wpv[24];
#pragma unroll
    for (int cc = 0; cc < 24; cc++) wpv[cc] = w_proj[co * CDIM + h * 24 + cc];
    __nv_bfloat16* A2 = g_A2 + (size_t)b * 256 * KTOT + (size_t)co * KTOT;
#pragma unroll
    for (int d = 0; d < 24; d++) {
        float a = 0.f;
#pragma unroll
        for (int cc = 0; cc < 24; cc++) a += wpv[cc] * at[cc][d];
        unsigned int pk = bfsplit_pack(a);
        __nv_bfloat16 hi = __ushort_as_bfloat16((unsigned short)(pk & 0xFFFF));
        __nv_bfloat16 lo = __ushort_as_bfloat16((unsigned short)(pk >> 16));
        A2[h * 24 + d] = hi;
        A2[192 + h * 24 + d] = hi;
        A2[384 + h * 24 + d] = lo;
    }
}

// ---------------- launch ----------------
extern "C" void kernel_launch(void* const* d_in, const int* in_sizes, int n_in,
                              void* d_out, int out_size) {
    const float* x           = (const float*)d_in[0];
    const float* w_dw        = (const float*)d_in[1];
    const float* w_qkv       = (const float*)d_in[2];
    const float* w_qkvdw     = (const float*)d_in[3];
    const float* w_proj      = (const float*)d_in[4];
    const float* temperature = (const float*)d_in[5];
    const float* rescale     = (const float*)d_in[6];
    float* out = (float*)d_out;

    float* p_qkv;
    __nv_bfloat16 *p_A1, *p_B1, *p_A2, *p_V;
    cudaGetSymbolAddress((void**)&p_qkv, g_qkv);
    cudaGetSymbolAddress((void**)&p_A1, g_A1);
    cudaGetSymbolAddress((void**)&p_B1, g_B1);
    cudaGetSymbolAddress((void**)&p_A2, g_A2);
    cudaGetSymbolAddress((void**)&p_V, g_V);

    static bool attr_set = false;
    if (!attr_set) {
        cudaFuncSetAttribute(k_fused_qk, cudaFuncAttributeMaxDynamicSharedMemorySize, 98304);
        cudaFuncSetAttribute(k_splitB, cudaFuncAttributeMaxDynamicSharedMemorySize, 66560);
        cudaFuncSetAttribute(k_dwv, cudaFuncAttributeMaxDynamicSharedMemorySize, 66560);
        attr_set = true;
    }

    // 1. variance of depthwise(x)
    k_var<<<BATCH * CDIM, 256>>>(x, w_dw);
    // 2. split/transpose x for GEMM1 B operand
    k_splitB<<<dim3(64, 3, BATCH), 256, 66560>>>(x);
    // 3. split w_qkv for GEMM1 A operand
    k_prepA1<<<C3, CDIM>>>(w_qkv);
    // 4. qkv = w_qkv @ x via HMMA bf16 split-K GEMM (M=576 pad 640, N=16384, K=576)
    k_gemm_mma<<<dim3(HW / BN, 5, BATCH), 256>>>(
        p_A1, p_B1, p_qkv, C3, 0LL, (long long)HW * KTOT, (long long)C3 * HW);
    // 5. fused depthwise(q,k) + partial qk dots + norm partials
    k_fused_qk<<<dim3(RBQK, BATCH * HEADS), 256, 98304>>>(w_qkvdw);
    // 6. depthwise(v) + split/transpose for GEMM2 B operand
    k_dwv<<<dim3(64, 3, BATCH), 256, 66560>>>(w_qkvdw);
    // 7. softmax finalize
    k_attn_fin<<<BATCH * HEADS, CH * 32>>>(temperature, rescale);
    // 8. fold proj into attn, split for GEMM2 A operand
    k_w2<<<BATCH * HEADS, CDIM>>>(w_proj);
    // 9. out = W2 @ v via HMMA (M=192 pad 256, N=16384, K=576)
    k_gemm_mma<<<dim3(HW / BN, 2, BATCH), 256>>>(
        p_A2, p_V, out, CDIM, 256LL * KTOT, (long long)HW * KTOT, (long long)CDIM * HW);
}

// round 7
// speedup vs baseline: 1.9516x; 1.3434x over previous
#include <cuda_runtime.h>
#include <cuda_bf16.h>
#include <cstdint>
#include <math.h>

#define BATCH 8
#define CDIM 192
#define C3 576
#define HEADS 8
#define CH 24
#define HW 16384
#define KTOT 576          // logical split-K: [Wh|Wh|Wl] x [xh|xl|xh(wrapped)]
#define KB_PHYS 384       // physical B width (hi|lo); k>=384 wraps to hi
#define RBQK 32

// ---------------- scratch ----------------
__device__ float g_qkv[BATCH * C3 * HW];                        // fp32 qkv (301 MB)
__device__ __nv_bfloat16 g_B1[(size_t)BATCH * HW * KB_PHYS];    // x split/transposed (100 MB)
__device__ __nv_bfloat16 g_V[(size_t)BATCH * HW * KB_PHYS];     // v dw split/transposed (100 MB)
__device__ __nv_bfloat16 g_A1[640 * KTOT];                      // w_qkv split (rows 576..639 = 0)
__device__ __nv_bfloat16 g_A2[BATCH * 256 * KTOT];              // W2 split (rows 192..255 = 0)
__device__ float g_var[BATCH * CDIM];
__device__ float g_attn_part[BATCH * HEADS * RBQK * CH * CH];
__device__ float g_nrm_part[BATCH * HEADS * RBQK * 48];
__device__ float g_attn[BATCH * HEADS * CH * CH];

// ---------------- helpers ----------------
__device__ __forceinline__ uint32_t smem_u32(const void* p) {
    uint32_t a;
    asm("{ .reg .u64 t; cvta.to.shared.u64 t, %1; cvt.u32.u64 %0, t; }" : "=r"(a) : "l"(p));
    return a;
}
#define CP_ASYNC16(s, g) \
    asm volatile("cp.async.cg.shared.global [%0], [%1], 16;" :: "r"(s), "l"(g) : "memory")
#define CP_COMMIT asm volatile("cp.async.commit_group;" ::: "memory")
#define CP_WAIT1 asm volatile("cp.async.wait_group 1;" ::: "memory")

__device__ __forceinline__ void ldm_x4(uint32_t* d, uint32_t addr) {
    asm volatile("ldmatrix.sync.aligned.m8n8.x4.shared.b16 {%0,%1,%2,%3}, [%4];"
                 : "=r"(d[0]), "=r"(d[1]), "=r"(d[2]), "=r"(d[3]) : "r"(addr));
}
__device__ __forceinline__ void mma16816(float* c, const uint32_t* a, uint32_t b0, uint32_t b1) {
    asm volatile(
        "mma.sync.aligned.m16n8k16.row.col.f32.bf16.bf16.f32 "
        "{%0,%1,%2,%3}, {%4,%5,%6,%7}, {%8,%9}, {%0,%1,%2,%3};"
        : "+f"(c[0]), "+f"(c[1]), "+f"(c[2]), "+f"(c[3])
        : "r"(a[0]), "r"(a[1]), "r"(a[2]), "r"(a[3]), "r"(b0), "r"(b1));
}
__device__ __forceinline__ uint32_t bfsplit_pack(float v) {
    __nv_bfloat16 hi = __float2bfloat16(v);
    __nv_bfloat16 lo = __float2bfloat16(v - __bfloat162float(hi));
    return (uint32_t)__bfloat16_as_ushort(hi) | ((uint32_t)__bfloat16_as_ushort(lo) << 16);
}

// ---------------- K1: depthwise 3x3 on x + unbiased variance ----------------
__global__ void k_var(const float* __restrict__ x, const float* __restrict__ w_dw) {
    int bc = blockIdx.x;
    const float* in = x + (size_t)bc * HW;
    const float* wp = w_dw + (bc % CDIM) * 9;
    float wv[9];
#pragma unroll
    for (int i = 0; i < 9; i++) wv[i] = wp[i];
    float s1 = 0.f, s2 = 0.f;
    for (int idx = threadIdx.x; idx < HW; idx += blockDim.x) {
        int y = idx >> 7, xx = idx & 127;
        float a = 0.f;
#pragma unroll
        for (int dy = 0; dy < 3; dy++) {
            int yy = y + dy - 1;
            if (yy < 0 || yy > 127) continue;
            const float* row = in + yy * 128;
#pragma unroll
            for (int dx = 0; dx < 3; dx++) {
                int xc = xx + dx - 1;
                if (xc < 0 || xc > 127) continue;
                a += wv[dy * 3 + dx] * row[xc];
            }
        }
        s1 += a; s2 += a * a;
    }
#pragma unroll
    for (int o = 16; o; o >>= 1) {
        s1 += __shfl_xor_sync(0xffffffffu, s1, o);
        s2 += __shfl_xor_sync(0xffffffffu, s2, o);
    }
    __shared__ float r1[8], r2[8];
    if ((threadIdx.x & 31) == 0) { r1[threadIdx.x >> 5] = s1; r2[threadIdx.x >> 5] = s2; }
    __syncthreads();
    if (threadIdx.x == 0) {
        float t1 = 0.f, t2 = 0.f;
#pragma unroll
        for (int i = 0; i < 8; i++) { t1 += r1[i]; t2 += r2[i]; }
        g_var[bc] = (t2 - t1 * t1 * (1.0f / 16384.0f)) * (1.0f / 16383.0f);
    }
}

// ---------------- K2: split+transpose x -> g_B1[b][n][384] = [xh | xl] ----------------
__global__ void k_splitB(const float* __restrict__ x) {
    extern __shared__ unsigned int sh[];   // [256][65]
    int nt = blockIdx.x, cg = blockIdx.y, b = blockIdx.z;
    int t = threadIdx.x;
    int n0 = nt * 256;
    const float* xb = x + ((size_t)b * CDIM + cg * 64) * HW + n0;
#pragma unroll 4
    for (int j = 0; j < 64; j++)
        sh[t * 65 + j] = bfsplit_pack(xb[(size_t)j * HW + t]);
    __syncthreads();
    __nv_bfloat16* Bb = g_B1 + (size_t)b * HW * KB_PHYS;
    int lane = t & 31, w = t >> 5;
    for (int r = w; r < 256; r += 8) {
        unsigned int e0 = sh[r * 65 + lane * 2];
        unsigned int e1 = sh[r * 65 + lane * 2 + 1];
        unsigned int hi2 = (e0 & 0xFFFFu) | (e1 << 16);
        unsigned int lo2 = (e0 >> 16) | (e1 & 0xFFFF0000u);
        size_t rowb = (size_t)(n0 + r) * KB_PHYS + cg * 64 + lane * 2;
        *(unsigned int*)(Bb + rowb) = hi2;
        *(unsigned int*)(Bb + rowb + 192) = lo2;
    }
}

// ---------------- K3: split w_qkv -> g_A1[m][576] = [Wh | Wh | Wl] ----------------
__global__ void k_prepA1(const float* __restrict__ w_qkv) {
    int m = blockIdx.x, c = threadIdx.x;
    unsigned int pk = bfsplit_pack(w_qkv[m * CDIM + c]);
    __nv_bfloat16 hi = __ushort_as_bfloat16((unsigned short)(pk & 0xFFFF));
    __nv_bfloat16 lo = __ushort_as_bfloat16((unsigned short)(pk >> 16));
    g_A1[m * KTOT + c] = hi;
    g_A1[m * KTOT + 192 + c] = hi;
    g_A1[m * KTOT + 384 + c] = lo;
}

// ---------------- K4: bf16 HMMA GEMM, 3-stage cp.async pipeline ----------------
#define BM 128
#define BN 128
#define BK 32
#define KITERS (KTOT / BK)     // 18
#define SROW 40
#define STAGES 3

__global__ __launch_bounds__(256)
void k_gemm_mma(const __nv_bfloat16* __restrict__ A, const __nv_bfloat16* __restrict__ B,
                float* __restrict__ C, int M_valid,
                long long sA, long long sB, long long sC) {
    extern __shared__ __nv_bfloat16 smbuf[];
    __nv_bfloat16* Asm = smbuf;                          // STAGES * BM * SROW
    __nv_bfloat16* Bsm = smbuf + STAGES * BM * SROW;     // STAGES * BN * SROW
    int tid = threadIdx.x, lane = tid & 31, wid = tid >> 5;
    int wm = wid & 1, wn = wid >> 1;
    int n0 = blockIdx.x * BN, m0 = blockIdx.y * BM, bz = blockIdx.z;
    const __nv_bfloat16* Ab = A + (size_t)bz * sA;
    const __nv_bfloat16* Bb = B + (size_t)bz * sB;
    float* Cb = C + (size_t)bz * sC;

    float acc[4][4][4];
#pragma unroll
    for (int im = 0; im < 4; im++)
#pragma unroll
        for (int in = 0; in < 4; in++)
#pragma unroll
            for (int q = 0; q < 4; q++) acc[im][in][q] = 0.f;

#define LOAD_STAGE(s, kk)                                                            \
    do {                                                                             \
        __nv_bfloat16* As_ = Asm + (s) * BM * SROW;                                  \
        __nv_bfloat16* Bs_ = Bsm + (s) * BN * SROW;                                  \
        int kb_ = ((kk) >= KB_PHYS) ? (kk) - KB_PHYS : (kk);                         \
        _Pragma("unroll")                                                            \
        for (int p = 0; p < 2; p++) {                                                \
            int i_ = tid + p * 256;                                                  \
            int r_ = i_ >> 2, cc_ = i_ & 3;                                          \
            CP_ASYNC16(smem_u32(As_ + r_ * SROW + cc_ * 8),                          \
                       Ab + (size_t)(m0 + r_) * KTOT + (kk) + cc_ * 8);              \
            CP_ASYNC16(smem_u32(Bs_ + r_ * SROW + cc_ * 8),                          \
                       Bb + (size_t)(n0 + r_) * KB_PHYS + kb_ + cc_ * 8);            \
        }                                                                            \
    } while (0)

    LOAD_STAGE(0, 0); CP_COMMIT;
    LOAD_STAGE(1, BK); CP_COMMIT;

    int stg = 0;
    for (int it = 0; it < KITERS; it++) {
        CP_WAIT1;
        __syncthreads();
        // prefetch it+2 into the stage consumed at it-1 (all warps past it-1 now)
        if (it + 2 < KITERS) {
            int nx = stg + 2; if (nx >= STAGES) nx -= STAGES;
            LOAD_STAGE(nx, (it + 2) * BK);
        }
        CP_COMMIT;
        __nv_bfloat16* As = Asm + stg * BM * SROW;
        __nv_bfloat16* Bs = Bsm + stg * BN * SROW;
#pragma unroll
        for (int ks = 0; ks < 2; ks++) {
            int k0 = ks * 16;
            uint32_t af[4][4];
#pragma unroll
            for (int im = 0; im < 4; im++) {
                uint32_t a = smem_u32(
                    As + (wm * 64 + im * 16 + (lane & 15)) * SROW + k0 + ((lane >> 4) << 3));
                ldm_x4(af[im], a);
            }
            uint32_t bf[2][4];
#pragma unroll
            for (int ip = 0; ip < 2; ip++) {
                uint32_t a = smem_u32(
                    Bs + (wn * 32 + ip * 16 + ((lane >> 4) << 3) + (lane & 7)) * SROW +
                    k0 + (lane & 8));
                ldm_x4(bf[ip], a);
            }
#pragma unroll
            for (int im = 0; im < 4; im++)
#pragma unroll
                for (int in = 0; in < 4; in++) {
                    int ip = in >> 1, sub = in & 1;
                    mma16816(acc[im][in], af[im], bf[ip][sub * 2], bf[ip][sub * 2 + 1]);
                }
        }
        stg = (stg + 1 == STAGES) ? 0 : stg + 1;
    }
#undef LOAD_STAGE

    int g = lane >> 2, tg = lane & 3;
#pragma unroll
    for (int im = 0; im < 4; im++) {
#pragma unroll
        for (int rr = 0; rr < 2; rr++) {
            int m = m0 + wm * 64 + im * 16 + g + rr * 8;
            if (m < M_valid) {
                float* dst = Cb + (size_t)m * HW + n0 + wn * 32 + tg * 2;
#pragma unroll
                for (int in = 0; in < 4; in++) {
                    float2 v = make_float2(acc[im][in][rr * 2], acc[im][in][rr * 2 + 1]);
                    *(float2*)(dst + in * 8) = v;
                }
            }
        }
    }
}

// ---------------- K5: fused dw(q,k) -> bf16 smem -> HMMA dots + fp32 norms ----------------
// smem: QK[64][520] bf16 (rows 0-23 Q, 24-31 zero, 32-55 K, 56-63 zero); reduce buf overlays.
#define QKROW 520
__global__ __launch_bounds__(256)
void k_fused_qk(const float* __restrict__ w_qkvdw) {
    extern __shared__ __nv_bfloat16 QK[];
    int rb = blockIdx.x, bh = blockIdx.y;
    int b = bh >> 3, h = bh & 7;
    int y0 = rb * 4;
    int tid = threadIdx.x, lane = tid & 31, w = tid >> 5;
    int xx = tid & 127, half = tid >> 7;

    // zero pad rows 24-31, 56-63
    for (int i = tid; i < 16 * QKROW; i += 256) {
        int r = i / QKROW, p = i - r * QKROW;
        int row = (r < 8) ? (24 + r) : (48 + r);
        QK[row * QKROW + p] = __float2bfloat16(0.f);
    }

    // conv: thread owns column xx, 4 output rows, channels half, half+2, ...
    for (int j = 0; j < 48; j += 2) {
        int cl = j + half;
        int ch = (cl < 24) ? (h * 24 + cl) : (192 + h * 24 + (cl - 24));
        const float* in = g_qkv + (((size_t)b * C3 + ch) << 14);
        const float* wp = w_qkvdw + ch * 9;
        float wv[9];
#pragma unroll
        for (int i = 0; i < 9; i++) wv[i] = wp[i];
        float o0 = 0.f, o1 = 0.f, o2 = 0.f, o3 = 0.f;
#pragma unroll
        for (int dy = -1; dy <= 4; dy++) {
            int iy = y0 + dy;
            if (iy < 0 || iy > 127) continue;
            const float* rowp = in + iy * 128;
            float m = rowp[xx];
            float l = (xx > 0) ? rowp[xx - 1] : 0.f;
            float r = (xx < 127) ? rowp[xx + 1] : 0.f;
#pragma unroll
            for (int o = 0; o < 4; o++) {
                int tap = dy - o + 1;
                if (tap >= 0 && tap < 3) {
                    float s = wv[tap * 3] * l + wv[tap * 3 + 1] * m + wv[tap * 3 + 2] * r;
                    if (o == 0) o0 += s;
                    else if (o == 1) o1 += s;
                    else if (o == 2) o2 += s;
                    else o3 += s;
                }
            }
        }
        int row_s = (cl < 24) ? cl : cl + 8;
        __nv_bfloat16* dst = QK + row_s * QKROW + xx;
        dst[0] = __float2bfloat16(o0);
        dst[128] = __float2bfloat16(o1);
        dst[256] = __float2bfloat16(o2);
        dst[384] = __float2bfloat16(o3);
    }
    __syncthreads();

    // fp32 norm partials from bf16 values (self-consistent with dots)
    {
        float* np = g_nrm_part + ((size_t)bh * RBQK + rb) * 48;
        for (int chl = w; chl < 48; chl += 8) {
            int row = (chl < 24) ? chl : chl + 8;
            float s = 0.f;
#pragma unroll
            for (int i = 0; i < 16; i++) {
                float v = __bfloat162float(QK[row * QKROW + lane + i * 32]);
                s += v * v;
            }
#pragma unroll
            for (int o = 16; o; o >>= 1) s += __shfl_xor_sync(0xffffffffu, s, o);
            if (lane == 0) np[chl] = s;
        }
    }

    // HMMA dots: warp w handles K range [w*64, w*64+64)
    float acc[2][4][4];
#pragma unroll
    for (int mt = 0; mt < 2; mt++)
#pragma unroll
        for (int n8 = 0; n8 < 4; n8++)
#pragma unroll
            for (int q = 0; q < 4; q++) acc[mt][n8][q] = 0.f;

#pragma unroll
    for (int kt = 0; kt < 4; kt++) {
        int k0 = w * 64 + kt * 16;
        uint32_t am[2][4];
#pragma unroll
        for (int mt = 0; mt < 2; mt++)
            ldm_x4(am[mt], smem_u32(QK + (mt * 16 + (lane & 15)) * QKROW + k0 +
                                    ((lane >> 4) << 3)));
        uint32_t bn[2][4];
#pragma unroll
        for (int nt = 0; nt < 2; nt++)
            ldm_x4(bn[nt], smem_u32(QK + (32 + nt * 16 + ((lane >> 4) << 3) + (lane & 7)) *
                                        QKROW + k0 + (lane & 8)));
#pragma unroll
        for (int mt = 0; mt < 2; mt++)
#pragma unroll
            for (int n8 = 0; n8 < 4; n8++) {
                int nt = n8 >> 1, sub = n8 & 1;
                mma16816(acc[mt][n8], am[mt], bn[nt][sub * 2], bn[nt][sub * 2 + 1]);
            }
    }
    __syncthreads();

    // reduce across warps via smem (overlays QK)
    float* rbuf = (float*)QK;   // 8 * 32 * 32 floats = 32 KB
    int g = lane >> 2, tg = lane & 3;
#pragma unroll
    for (int mt = 0; mt < 2; mt++)
#pragma unroll
        for (int n8 = 0; n8 < 4; n8++) {
            float* base = rbuf + w * 1024 + (mt * 16 + g) * 32 + n8 * 8 + tg * 2;
            base[0] = acc[mt][n8][0];
            base[1] = acc[mt][n8][1];
            base[8 * 32] = acc[mt][n8][2];
            base[8 * 32 + 1] = acc[mt][n8][3];
        }
    __syncthreads();
    float* ap = g_attn_part + ((size_t)bh * RBQK + rb) * 576;
    for (int i = tid; i < 576; i += 256) {
        int c = i / 24, d = i - c * 24;
        float s = 0.f;
#pragma unroll
        for (int w8 = 0; w8 < 8; w8++) s += rbuf[w8 * 1024 + c * 32 + d];
        ap[i] = s;
    }
}

// ---------------- K6: depthwise(v) + split + transpose -> g_V[b][n][384] ----------------
__global__ void k_dwv(const float* __restrict__ w_qkvdw) {
    extern __shared__ unsigned int sh[];   // [256][65]
    int rp = blockIdx.x, cg = blockIdx.y, b = blockIdx.z;
    int t = threadIdx.x;
    int y0 = rp * 2;
    int y = y0 + (t >> 7), xx = t & 127;
    for (int j = 0; j < 64; j++) {
        int ch = 384 + cg * 64 + j;
        const float* in = g_qkv + (((size_t)b * C3 + ch) << 14);
        const float* wp = w_qkvdw + ch * 9;
        float wv[9];
#pragma unroll
        for (int i = 0; i < 9; i++) wv[i] = wp[i];
        float a = 0.f;
#pragma unroll
        for (int dy = 0; dy < 3; dy++) {
            int yy = y + dy - 1;
            if (yy < 0 || yy > 127) continue;
            const float* row = in + yy * 128;
#pragma unroll
            for (int dx = 0; dx < 3; dx++) {
                int xc = xx + dx - 1;
                if (xc < 0 || xc > 127) continue;
                a += wv[dy * 3 + dx] * row[xc];
            }
        }
        sh[t * 65 + j] = bfsplit_pack(a);
    }
    __syncthreads();
    __nv_bfloat16* Vb = g_V + (size_t)b * HW * KB_PHYS;
    int lane = t & 31, w = t >> 5;
    int n0 = y0 * 128;
    for (int r = w; r < 256; r += 8) {
        unsigned int e0 = sh[r * 65 + lane * 2];
        unsigned int e1 = sh[r * 65 + lane * 2 + 1];
        unsigned int hi2 = (e0 & 0xFFFFu) | (e1 << 16);
        unsigned int lo2 = (e0 >> 16) | (e1 & 0xFFFF0000u);
        size_t rowb = (size_t)(n0 + r) * KB_PHYS + cg * 64 + lane * 2;
        *(unsigned int*)(Vb + rowb) = hi2;
        *(unsigned int*)(Vb + rowb + 192) = lo2;
    }
}

// ---------------- K7: finalize attention ----------------
__global__ void k_attn_fin(const float* __restrict__ temperature,
                           const float* __restrict__ rescale) {
    int bh = blockIdx.x;
    int b = bh >> 3, h = bh & 7;
    int c = threadIdx.x >> 5, lane = threadIdx.x & 31;
    float val;
    if (lane < 24) {
        float raw = 0.f, nq2 = 0.f, nk2 = 0.f;
        for (int s = 0; s < RBQK; s++) {
            const float* ap = g_attn_part + ((size_t)bh * RBQK + s) * 576;
            const float* np = g_nrm_part + ((size_t)bh * RBQK + s) * 48;
            raw += ap[c * 24 + lane];
            nq2 += np[c];
            nk2 += np[24 + lane];
        }
        float nq = sqrtf(nq2), nk = sqrtf(nk2);
        val = raw / (fmaxf(nq, 1e-12f) * fmaxf(nk, 1e-12f)) * temperature[h];
        if (c == lane) val += rescale[h] * g_var[b * CDIM + h * 24 + c];
    } else {
        val = -INFINITY;
    }
    float mx = val;
#pragma unroll
    for (int o = 16; o; o >>= 1) mx = fmaxf(mx, __shfl_xor_sync(0xffffffffu, mx, o));
    float ex = (lane < 24) ? expf(val - mx) : 0.f;
    float sm = ex;
#pragma unroll
    for (int o = 16; o; o >>= 1) sm += __shfl_xor_sync(0xffffffffu, sm, o);
    if (lane < 24) g_attn[(size_t)bh * 576 + c * 24 + lane] = ex / sm;
}

// ---------------- K8: W2 = w_proj @ blockdiag(attn) -> g_A2 [Wh | Wh | Wl] ----------------
__global__ void k_w2(const float* __restrict__ w_proj) {
    int bh = blockIdx.x;
    int b = bh >> 3, h = bh & 7;
    int co = threadIdx.x;
    __shared__ float at[24][24];
    for (int i = co; i < 576; i += 192) at[i / 24][i % 24] = g_attn[(size_t)bh * 576 + i];
    __syncthreads();
    float wpv[24];
#pragma unroll
    for (int cc = 0; cc < 24; cc++) wpv[cc] = w_proj[co * CDIM + h * 24 + cc];
    __nv_bfloat16* A2 = g_A2 + (size_t)b * 256 * KTOT + (size_t)co * KTOT;
#pragma unroll
    for (int d = 0; d < 24; d++) {
        float a = 0.f;
#pragma unroll
        for (int cc = 0; cc < 24; cc++) a += wpv[cc] * at[cc][d];
        unsigned int pk = bfsplit_pack(a);
        A2[h * 24 + d] = __ushort_as_bfloat16((unsigned short)(pk & 0xFFFF));
        A2[192 + h * 24 + d] = __ushort_as_bfloat16((unsigned short)(pk & 0xFFFF));
        A2[384 + h * 24 + d] = __ushort_as_bfloat16((unsigned short)(pk >> 16));
    }
}

// ---------------- launch ----------------
extern "C" void kernel_launch(void* const* d_in, const int* in_sizes, int n_in,
                              void* d_out, int out_size) {
    const float* x           = (const float*)d_in[0];
    const float* w_dw        = (const float*)d_in[1];
    const float* w_qkv       = (const float*)d_in[2];
    const float* w_qkvdw     = (const float*)d_in[3];
    const float* w_proj      = (const float*)d_in[4];
    const float* temperature = (const float*)d_in[5];
    const float* rescale     = (const float*)d_in[6];
    float* out = (float*)d_out;

    float* p_qkv;
    __nv_bfloat16 *p_A1, *p_B1, *p_A2, *p_V;
    cudaGetSymbolAddress((void**)&p_qkv, g_qkv);
    cudaGetSymbolAddress((void**)&p_A1, g_A1);
    cudaGetSymbolAddress((void**)&p_B1, g_B1);
    cudaGetSymbolAddress((void**)&p_A2, g_A2);
    cudaGetSymbolAddress((void**)&p_V, g_V);

    const int GEMM_SMEM = STAGES * (BM + BN) * SROW * 2;   // 61440
    const int QK_SMEM = 64 * QKROW * 2;                    // 66560
    static bool attr_set = false;
    if (!attr_set) {
        cudaFuncSetAttribute(k_gemm_mma, cudaFuncAttributeMaxDynamicSharedMemorySize, GEMM_SMEM);
        cudaFuncSetAttribute(k_fused_qk, cudaFuncAttributeMaxDynamicSharedMemorySize, QK_SMEM);
        cudaFuncSetAttribute(k_splitB, cudaFuncAttributeMaxDynamicSharedMemorySize, 66560);
        cudaFuncSetAttribute(k_dwv, cudaFuncAttributeMaxDynamicSharedMemorySize, 66560);
        attr_set = true;
    }

    k_var<<<BATCH * CDIM, 256>>>(x, w_dw);
    k_splitB<<<dim3(64, 3, BATCH), 256, 66560>>>(x);
    k_prepA1<<<C3, CDIM>>>(w_qkv);
    k_gemm_mma<<<dim3(HW / BN, 5, BATCH), 256, GEMM_SMEM>>>(
        p_A1, p_B1, p_qkv, C3, 0LL, (long long)HW * KB_PHYS, (long long)C3 * HW);
    k_fused_qk<<<dim3(RBQK, BATCH * HEADS), 256, QK_SMEM>>>(w_qkvdw);
    k_dwv<<<dim3(64, 3, BATCH), 256, 66560>>>(w_qkvdw);
    k_attn_fin<<<BATCH * HEADS, CH * 32>>>(temperature, rescale);
    k_w2<<<BATCH * HEADS, CDIM>>>(w_proj);
    k_gemm_mma<<<dim3(HW / BN, 2, BATCH), 256, GEMM_SMEM>>>(
        p_A2, p_V, out, CDIM, 256LL * KTOT, (long long)HW * KB_PHYS, (long long)CDIM * HW);
}

// round 8
// speedup vs baseline: 1.9718x; 1.0104x over previous
#include <cuda_runtime.h>
#include <cuda_bf16.h>
#include <cstdint>
#include <math.h>

#define BATCH 8
#define CDIM 192
#define C3 576
#define HEADS 8
#define CH 24
#define HW 16384
#define KTOT 576          // logical split-K: [Wh|Wh|Wl] x [xh|xl|xh(wrapped)]
#define KB_PHYS 384       // physical B width (hi|lo); k>=384 wraps to hi
#define RBQK 32

// ---------------- scratch ----------------
__device__ float g_qkv[BATCH * C3 * HW];                        // fp32 qkv (301 MB)
__device__ __nv_bfloat16 g_B1[(size_t)BATCH * HW * KB_PHYS];    // x split/transposed (100 MB)
__device__ __nv_bfloat16 g_V[(size_t)BATCH * HW * KB_PHYS];     // v dw split/transposed (100 MB)
__device__ __nv_bfloat16 g_A1[640 * KTOT];                      // w_qkv split (rows 576..639 = 0)
__device__ __nv_bfloat16 g_A2[BATCH * 256 * KTOT];              // W2 split (rows 192..255 = 0)
__device__ float g_var[BATCH * CDIM];
__device__ float g_attn_part[BATCH * HEADS * RBQK * CH * CH];
__device__ float g_nrm_part[BATCH * HEADS * RBQK * 48];
__device__ float g_attn[BATCH * HEADS * CH * CH];

// ---------------- helpers ----------------
__device__ __forceinline__ uint32_t smem_u32(const void* p) {
    uint32_t a;
    asm("{ .reg .u64 t; cvta.to.shared.u64 t, %1; cvt.u32.u64 %0, t; }" : "=r"(a) : "l"(p));
    return a;
}
#define CP_ASYNC16(s, g) \
    asm volatile("cp.async.cg.shared.global [%0], [%1], 16;" :: "r"(s), "l"(g) : "memory")
#define CP_COMMIT asm volatile("cp.async.commit_group;" ::: "memory")
#define CP_WAIT1 asm volatile("cp.async.wait_group 1;" ::: "memory")

__device__ __forceinline__ void ldm_x4(uint32_t* d, uint32_t addr) {
    asm volatile("ldmatrix.sync.aligned.m8n8.x4.shared.b16 {%0,%1,%2,%3}, [%4];"
                 : "=r"(d[0]), "=r"(d[1]), "=r"(d[2]), "=r"(d[3]) : "r"(addr));
}
__device__ __forceinline__ void mma16816(float* c, const uint32_t* a, uint32_t b0, uint32_t b1) {
    asm volatile(
        "mma.sync.aligned.m16n8k16.row.col.f32.bf16.bf16.f32 "
        "{%0,%1,%2,%3}, {%4,%5,%6,%7}, {%8,%9}, {%0,%1,%2,%3};"
        : "+f"(c[0]), "+f"(c[1]), "+f"(c[2]), "+f"(c[3])
        : "r"(a[0]), "r"(a[1]), "r"(a[2]), "r"(a[3]), "r"(b0), "r"(b1));
}
__device__ __forceinline__ uint32_t bfsplit_pack(float v) {
    __nv_bfloat16 hi = __float2bfloat16(v);
    __nv_bfloat16 lo = __float2bfloat16(v - __bfloat162float(hi));
    return (uint32_t)__bfloat16_as_ushort(hi) | ((uint32_t)__bfloat16_as_ushort(lo) << 16);
}

// ---------------- K1: depthwise 3x3 on x + unbiased variance ----------------
__global__ void k_var(const float* __restrict__ x, const float* __restrict__ w_dw) {
    int bc = blockIdx.x;
    const float* in = x + (size_t)bc * HW;
    const float* wp = w_dw + (bc % CDIM) * 9;
    float wv[9];
#pragma unroll
    for (int i = 0; i < 9; i++) wv[i] = wp[i];
    float s1 = 0.f, s2 = 0.f;
    for (int idx = threadIdx.x; idx < HW; idx += blockDim.x) {
        int y = idx >> 7, xx = idx & 127;
        float a = 0.f;
#pragma unroll
        for (int dy = 0; dy < 3; dy++) {
            int yy = y + dy - 1;
            if (yy < 0 || yy > 127) continue;
            const float* row = in + yy * 128;
#pragma unroll
            for (int dx = 0; dx < 3; dx++) {
                int xc = xx + dx - 1;
                if (xc < 0 || xc > 127) continue;
                a += wv[dy * 3 + dx] * row[xc];
            }
        }
        s1 += a; s2 += a * a;
    }
#pragma unroll
    for (int o = 16; o; o >>= 1) {
        s1 += __shfl_xor_sync(0xffffffffu, s1, o);
        s2 += __shfl_xor_sync(0xffffffffu, s2, o);
    }
    __shared__ float r1[8], r2[8];
    if ((threadIdx.x & 31) == 0) { r1[threadIdx.x >> 5] = s1; r2[threadIdx.x >> 5] = s2; }
    __syncthreads();
    if (threadIdx.x == 0) {
        float t1 = 0.f, t2 = 0.f;
#pragma unroll
        for (int i = 0; i < 8; i++) { t1 += r1[i]; t2 += r2[i]; }
        g_var[bc] = (t2 - t1 * t1 * (1.0f / 16384.0f)) * (1.0f / 16383.0f);
    }
}

// ---------------- K2: split+transpose x -> g_B1[b][n][384] = [xh | xl] ----------------
__global__ void k_splitB(const float* __restrict__ x) {
    extern __shared__ unsigned int sh[];   // [256][65]
    int nt = blockIdx.x, cg = blockIdx.y, b = blockIdx.z;
    int t = threadIdx.x;
    int n0 = nt * 256;
    const float* xb = x + ((size_t)b * CDIM + cg * 64) * HW + n0;
#pragma unroll 4
    for (int j = 0; j < 64; j++)
        sh[t * 65 + j] = bfsplit_pack(xb[(size_t)j * HW + t]);
    __syncthreads();
    __nv_bfloat16* Bb = g_B1 + (size_t)b * HW * KB_PHYS;
    int lane = t & 31, w = t >> 5;
    for (int r = w; r < 256; r += 8) {
        unsigned int e0 = sh[r * 65 + lane * 2];
        unsigned int e1 = sh[r * 65 + lane * 2 + 1];
        unsigned int hi2 = (e0 & 0xFFFFu) | (e1 << 16);
        unsigned int lo2 = (e0 >> 16) | (e1 & 0xFFFF0000u);
        size_t rowb = (size_t)(n0 + r) * KB_PHYS + cg * 64 + lane * 2;
        *(unsigned int*)(Bb + rowb) = hi2;
        *(unsigned int*)(Bb + rowb + 192) = lo2;
    }
}

// ---------------- K3: split w_qkv -> g_A1[m][576] = [Wh | Wh | Wl] ----------------
__global__ void k_prepA1(const float* __restrict__ w_qkv) {
    int m = blockIdx.x, c = threadIdx.x;
    unsigned int pk = bfsplit_pack(w_qkv[m * CDIM + c]);
    __nv_bfloat16 hi = __ushort_as_bfloat16((unsigned short)(pk & 0xFFFF));
    __nv_bfloat16 lo = __ushort_as_bfloat16((unsigned short)(pk >> 16));
    g_A1[m * KTOT + c] = hi;
    g_A1[m * KTOT + 192 + c] = hi;
    g_A1[m * KTOT + 384 + c] = lo;
}

// ---------------- K4: bf16 HMMA GEMM, BK=64, 3-stage pipeline + frag double-buffer ----------------
#define BM 128
#define BN 128
#define BK 64
#define KITERS (KTOT / BK)     // 9
#define SROW 72                // 64 + 8 pad halves: 144B rows -> conflict-free ldmatrix
#define STAGES 3

__global__ __launch_bounds__(256)
void k_gemm_mma(const __nv_bfloat16* __restrict__ A, const __nv_bfloat16* __restrict__ B,
                float* __restrict__ C, int M_valid,
                long long sA, long long sB, long long sC) {
    extern __shared__ __nv_bfloat16 smbuf[];
    __nv_bfloat16* Asm = smbuf;                          // STAGES * BM * SROW
    __nv_bfloat16* Bsm = smbuf + STAGES * BM * SROW;     // STAGES * BN * SROW
    int tid = threadIdx.x, lane = tid & 31, wid = tid >> 5;
    int wm = wid & 1, wn = wid >> 1;
    int n0 = blockIdx.x * BN, m0 = blockIdx.y * BM, bz = blockIdx.z;
    const __nv_bfloat16* Ab = A + (size_t)bz * sA;
    const __nv_bfloat16* Bb = B + (size_t)bz * sB;
    float* Cb = C + (size_t)bz * sC;

    float acc[4][4][4];
#pragma unroll
    for (int im = 0; im < 4; im++)
#pragma unroll
        for (int in = 0; in < 4; in++)
#pragma unroll
            for (int q = 0; q < 4; q++) acc[im][in][q] = 0.f;

#define LOAD_STAGE(s, kk)                                                            \
    do {                                                                             \
        __nv_bfloat16* As_ = Asm + (s) * BM * SROW;                                  \
        __nv_bfloat16* Bs_ = Bsm + (s) * BN * SROW;                                  \
        int kb_ = ((kk) >= KB_PHYS) ? (kk) - KB_PHYS : (kk);                         \
        _Pragma("unroll")                                                            \
        for (int p = 0; p < 4; p++) {                                                \
            int i_ = tid + p * 256;                                                  \
            int r_ = i_ >> 3, cc_ = i_ & 7;                                          \
            CP_ASYNC16(smem_u32(As_ + r_ * SROW + cc_ * 8),                          \
                       Ab + (size_t)(m0 + r_) * KTOT + (kk) + cc_ * 8);              \
            CP_ASYNC16(smem_u32(Bs_ + r_ * SROW + cc_ * 8),                          \
                       Bb + (size_t)(n0 + r_) * KB_PHYS + kb_ + cc_ * 8);            \
        }                                                                            \
    } while (0)

    LOAD_STAGE(0, 0); CP_COMMIT;
    LOAD_STAGE(1, BK); CP_COMMIT;

    int stg = 0;
    for (int it = 0; it < KITERS; it++) {
        CP_WAIT1;
        __syncthreads();
        if (it + 2 < KITERS) {
            int nx = stg + 2; if (nx >= STAGES) nx -= STAGES;
            LOAD_STAGE(nx, (it + 2) * BK);
        }
        CP_COMMIT;
        const __nv_bfloat16* As = Asm + stg * BM * SROW;
        const __nv_bfloat16* Bs = Bsm + stg * BN * SROW;

        uint32_t af[2][4][4], bfr[2][2][4];
#define LDFRAG(ks, buf)                                                              \
    do {                                                                             \
        int k0_ = (ks) * 16;                                                         \
        _Pragma("unroll")                                                            \
        for (int im = 0; im < 4; im++)                                               \
            ldm_x4(af[buf][im],                                                      \
                   smem_u32(As + (wm * 64 + im * 16 + (lane & 15)) * SROW + k0_ +    \
                            ((lane >> 4) << 3)));                                    \
        _Pragma("unroll")                                                            \
        for (int ip = 0; ip < 2; ip++)                                               \
            ldm_x4(bfr[buf][ip],                                                     \
                   smem_u32(Bs + (wn * 32 + ip * 16 + ((lane >> 4) << 3) +           \
                                  (lane & 7)) * SROW + k0_ + (lane & 8)));           \
    } while (0)

        LDFRAG(0, 0);
#pragma unroll
        for (int ks = 0; ks < 4; ks++) {
            if (ks < 3) LDFRAG(ks + 1, (ks + 1) & 1);
            int bsel = ks & 1;
#pragma unroll
            for (int im = 0; im < 4; im++)
#pragma unroll
                for (int in = 0; in < 4; in++) {
                    int ip = in >> 1, sub = in & 1;
                    mma16816(acc[im][in], af[bsel][im],
                             bfr[bsel][ip][sub * 2], bfr[bsel][ip][sub * 2 + 1]);
                }
        }
#undef LDFRAG
        stg = (stg + 1 == STAGES) ? 0 : stg + 1;
    }
#undef LOAD_STAGE

    int g = lane >> 2, tg = lane & 3;
#pragma unroll
    for (int im = 0; im < 4; im++) {
#pragma unroll
        for (int rr = 0; rr < 2; rr++) {
            int m = m0 + wm * 64 + im * 16 + g + rr * 8;
            if (m < M_valid) {
                float* dst = Cb + (size_t)m * HW + n0 + wn * 32 + tg * 2;
#pragma unroll
                for (int in = 0; in < 4; in++) {
                    float2 v = make_float2(acc[im][in][rr * 2], acc[im][in][rr * 2 + 1]);
                    *(float2*)(dst + in * 8) = v;
                }
            }
        }
    }
}

// ---------------- K5: fused dw(q,k) -> bf16 smem -> HMMA dots + fp32 norms ----------------
#define QKROW 520
__global__ __launch_bounds__(256)
void k_fused_qk(const float* __restrict__ w_qkvdw) {
    extern __shared__ __nv_bfloat16 QK[];
    int rb = blockIdx.x, bh = blockIdx.y;
    int b = bh >> 3, h = bh & 7;
    int y0 = rb * 4;
    int tid = threadIdx.x, lane = tid & 31, w = tid >> 5;
    int xx = tid & 127, half = tid >> 7;

    for (int i = tid; i < 16 * QKROW; i += 256) {
        int r = i / QKROW, p = i - r * QKROW;
        int row = (r < 8) ? (24 + r) : (48 + r);
        QK[row * QKROW + p] = __float2bfloat16(0.f);
    }

    for (int j = 0; j < 48; j += 2) {
        int cl = j + half;
        int ch = (cl < 24) ? (h * 24 + cl) : (192 + h * 24 + (cl - 24));
        const float* in = g_qkv + (((size_t)b * C3 + ch) << 14);
        const float* wp = w_qkvdw + ch * 9;
        float wv[9];
#pragma unroll
        for (int i = 0; i < 9; i++) wv[i] = wp[i];
        float o0 = 0.f, o1 = 0.f, o2 = 0.f, o3 = 0.f;
#pragma unroll
        for (int dy = -1; dy <= 4; dy++) {
            int iy = y0 + dy;
            if (iy < 0 || iy > 127) continue;
            const float* rowp = in + iy * 128;
            float m = rowp[xx];
            float l = (xx > 0) ? rowp[xx - 1] : 0.f;
            float r = (xx < 127) ? rowp[xx + 1] : 0.f;
#pragma unroll
            for (int o = 0; o < 4; o++) {
                int tap = dy - o + 1;
                if (tap >= 0 && tap < 3) {
                    float s = wv[tap * 3] * l + wv[tap * 3 + 1] * m + wv[tap * 3 + 2] * r;
                    if (o == 0) o0 += s;
                    else if (o == 1) o1 += s;
                    else if (o == 2) o2 += s;
                    else o3 += s;
                }
            }
        }
        int row_s = (cl < 24) ? cl : cl + 8;
        __nv_bfloat16* dst = QK + row_s * QKROW + xx;
        dst[0] = __float2bfloat16(o0);
        dst[128] = __float2bfloat16(o1);
        dst[256] = __float2bfloat16(o2);
        dst[384] = __float2bfloat16(o3);
    }
    __syncthreads();

    {
        float* np = g_nrm_part + ((size_t)bh * RBQK + rb) * 48;
        for (int chl = w; chl < 48; chl += 8) {
            int row = (chl < 24) ? chl : chl + 8;
            float s = 0.f;
#pragma unroll
            for (int i = 0; i < 16; i++) {
                float v = __bfloat162float(QK[row * QKROW + lane + i * 32]);
                s += v * v;
            }
#pragma unroll
            for (int o = 16; o; o >>= 1) s += __shfl_xor_sync(0xffffffffu, s, o);
            if (lane == 0) np[chl] = s;
        }
    }

    float acc[2][4][4];
#pragma unroll
    for (int mt = 0; mt < 2; mt++)
#pragma unroll
        for (int n8 = 0; n8 < 4; n8++)
#pragma unroll
            for (int q = 0; q < 4; q++) acc[mt][n8][q] = 0.f;

#pragma unroll
    for (int kt = 0; kt < 4; kt++) {
        int k0 = w * 64 + kt * 16;
        uint32_t am[2][4];
#pragma unroll
        for (int mt = 0; mt < 2; mt++)
            ldm_x4(am[mt], smem_u32(QK + (mt * 16 + (lane & 15)) * QKROW + k0 +
                                    ((lane >> 4) << 3)));
        uint32_t bn[2][4];
#pragma unroll
        for (int nt = 0; nt < 2; nt++)
            ldm_x4(bn[nt], smem_u32(QK + (32 + nt * 16 + ((lane >> 4) << 3) + (lane & 7)) *
                                        QKROW + k0 + (lane & 8)));
#pragma unroll
        for (int mt = 0; mt < 2; mt++)
#pragma unroll
            for (int n8 = 0; n8 < 4; n8++) {
                int nt = n8 >> 1, sub = n8 & 1;
                mma16816(acc[mt][n8], am[mt], bn[nt][sub * 2], bn[nt][sub * 2 + 1]);
            }
    }
    __syncthreads();

    float* rbuf = (float*)QK;
    int g = lane >> 2, tg = lane & 3;
#pragma unroll
    for (int mt = 0; mt < 2; mt++)
#pragma unroll
        for (int n8 = 0; n8 < 4; n8++) {
            float* base = rbuf + w * 1024 + (mt * 16 + g) * 32 + n8 * 8 + tg * 2;
            base[0] = acc[mt][n8][0];
            base[1] = acc[mt][n8][1];
            base[8 * 32] = acc[mt][n8][2];
            base[8 * 32 + 1] = acc[mt][n8][3];
        }
    __syncthreads();
    float* ap = g_attn_part + ((size_t)bh * RBQK + rb) * 576;
    for (int i = tid; i < 576; i += 256) {
        int c = i / 24, d = i - c * 24;
        float s = 0.f;
#pragma unroll
        for (int w8 = 0; w8 < 8; w8++) s += rbuf[w8 * 1024 + c * 32 + d];
        ap[i] = s;
    }
}

// ---------------- K6: depthwise(v) + split + transpose -> g_V[b][n][384] ----------------
__global__ void k_dwv(const float* __restrict__ w_qkvdw) {
    extern __shared__ unsigned int sh[];   // [256][65]
    int rp = blockIdx.x, cg = blockIdx.y, b = blockIdx.z;
    int t = threadIdx.x;
    int y0 = rp * 2;
    int y = y0 + (t >> 7), xx = t & 127;
    for (int j = 0; j < 64; j++) {
        int ch = 384 + cg * 64 + j;
        const float* in = g_qkv + (((size_t)b * C3 + ch) << 14);
        const float* wp = w_qkvdw + ch * 9;
        float wv[9];
#pragma unroll
        for (int i = 0; i < 9; i++) wv[i] = wp[i];
        float a = 0.f;
#pragma unroll
        for (int dy = 0; dy < 3; dy++) {
            int yy = y + dy - 1;
            if (yy < 0 || yy > 127) continue;
            const float* row = in + yy * 128;
#pragma unroll
            for (int dx = 0; dx < 3; dx++) {
                int xc = xx + dx - 1;
                if (xc < 0 || xc > 127) continue;
                a += wv[dy * 3 + dx] * row[xc];
            }
        }
        sh[t * 65 + j] = bfsplit_pack(a);
    }
    __syncthreads();
    __nv_bfloat16* Vb = g_V + (size_t)b * HW * KB_PHYS;
    int lane = t & 31, w = t >> 5;
    int n0 = y0 * 128;
    for (int r = w; r < 256; r += 8) {
        unsigned int e0 = sh[r * 65 + lane * 2];
        unsigned int e1 = sh[r * 65 + lane * 2 + 1];
        unsigned int hi2 = (e0 & 0xFFFFu) | (e1 << 16);
        unsigned int lo2 = (e0 >> 16) | (e1 & 0xFFFF0000u);
        size_t rowb = (size_t)(n0 + r) * KB_PHYS + cg * 64 + lane * 2;
        *(unsigned int*)(Vb + rowb) = hi2;
        *(unsigned int*)(Vb + rowb + 192) = lo2;
    }
}

// ---------------- K7: finalize attention ----------------
__global__ void k_attn_fin(const float* __restrict__ temperature,
                           const float* __restrict__ rescale) {
    int bh = blockIdx.x;
    int b = bh >> 3, h = bh & 7;
    int c = threadIdx.x >> 5, lane = threadIdx.x & 31;
    float val;
    if (lane < 24) {
        float raw = 0.f, nq2 = 0.f, nk2 = 0.f;
        for (int s = 0; s < RBQK; s++) {
            const float* ap = g_attn_part + ((size_t)bh * RBQK + s) * 576;
            const float* np = g_nrm_part + ((size_t)bh * RBQK + s) * 48;
            raw += ap[c * 24 + lane];
            nq2 += np[c];
            nk2 += np[24 + lane];
        }
        float nq = sqrtf(nq2), nk = sqrtf(nk2);
        val = raw / (fmaxf(nq, 1e-12f) * fmaxf(nk, 1e-12f)) * temperature[h];
        if (c == lane) val += rescale[h] * g_var[b * CDIM + h * 24 + c];
    } else {
        val = -INFINITY;
    }
    float mx = val;
#pragma unroll
    for (int o = 16; o; o >>= 1) mx = fmaxf(mx, __shfl_xor_sync(0xffffffffu, mx, o));
    float ex = (lane < 24) ? expf(val - mx) : 0.f;
    float sm = ex;
#pragma unroll
    for (int o = 16; o; o >>= 1) sm += __shfl_xor_sync(0xffffffffu, sm, o);
    if (lane < 24) g_attn[(size_t)bh * 576 + c * 24 + lane] = ex / sm;
}

// ---------------- K8: W2 = w_proj @ blockdiag(attn) -> g_A2 [Wh | Wh | Wl] ----------------
__global__ void k_w2(const float* __restrict__ w_proj) {
    int bh = blockIdx.x;
    int b = bh >> 3, h = bh & 7;
    int co = threadIdx.x;
    __shared__ float at[24][24];
    for (int i = co; i < 576; i += 192) at[i / 24][i % 24] = g_attn[(size_t)bh * 576 + i];
    __syncthreads();
    float wpv[24];
#pragma unroll
    for (int cc = 0; cc < 24; cc++) wpv[cc] = w_proj[co * CDIM + h * 24 + cc];
    __nv_bfloat16* A2 = g_A2 + (size_t)b * 256 * KTOT + (size_t)co * KTOT;
#pragma unroll
    for (int d = 0; d < 24; d++) {
        float a = 0.f;
#pragma unroll
        for (int cc = 0; cc < 24; cc++) a += wpv[cc] * at[cc][d];
        unsigned int pk = bfsplit_pack(a);
        A2[h * 24 + d] = __ushort_as_bfloat16((unsigned short)(pk & 0xFFFF));
        A2[192 + h * 24 + d] = __ushort_as_bfloat16((unsigned short)(pk & 0xFFFF));
        A2[384 + h * 24 + d] = __ushort_as_bfloat16((unsigned short)(pk >> 16));
    }
}

// ---------------- launch ----------------
extern "C" void kernel_launch(void* const* d_in, const int* in_sizes, int n_in,
                              void* d_out, int out_size) {
    const float* x           = (const float*)d_in[0];
    const float* w_dw        = (const float*)d_in[1];
    const float* w_qkv       = (const float*)d_in[2];
    const float* w_qkvdw     = (const float*)d_in[3];
    const float* w_proj      = (const float*)d_in[4];
    const float* temperature = (const float*)d_in[5];
    const float* rescale     = (const float*)d_in[6];
    float* out = (float*)d_out;

    float* p_qkv;
    __nv_bfloat16 *p_A1, *p_B1, *p_A2, *p_V;
    cudaGetSymbolAddress((void**)&p_qkv, g_qkv);
    cudaGetSymbolAddress((void**)&p_A1, g_A1);
    cudaGetSymbolAddress((void**)&p_B1, g_B1);
    cudaGetSymbolAddress((void**)&p_A2, g_A2);
    cudaGetSymbolAddress((void**)&p_V, g_V);

    const int GEMM_SMEM = STAGES * (BM + BN) * SROW * 2;   // 110592
    const int QK_SMEM = 64 * QKROW * 2;                    // 66560
    static bool attr_set = false;
    if (!attr_set) {
        cudaFuncSetAttribute(k_gemm_mma, cudaFuncAttributeMaxDynamicSharedMemorySize, GEMM_SMEM);
        cudaFuncSetAttribute(k_fused_qk, cudaFuncAttributeMaxDynamicSharedMemorySize, QK_SMEM);
        cudaFuncSetAttribute(k_splitB, cudaFuncAttributeMaxDynamicSharedMemorySize, 66560);
        cudaFuncSetAttribute(k_dwv, cudaFuncAttributeMaxDynamicSharedMemorySize, 66560);
        attr_set = true;
    }

    k_var<<<BATCH * CDIM, 256>>>(x, w_dw);
    k_splitB<<<dim3(64, 3, BATCH), 256, 66560>>>(x);
    k_prepA1<<<C3, CDIM>>>(w_qkv);
    k_gemm_mma<<<dim3(HW / BN, 5, BATCH), 256, GEMM_SMEM>>>(
        p_A1, p_B1, p_qkv, C3, 0LL, (long long)HW * KB_PHYS, (long long)C3 * HW);
    k_fused_qk<<<dim3(RBQK, BATCH * HEADS), 256, QK_SMEM>>>(w_qkvdw);
    k_dwv<<<dim3(64, 3, BATCH), 256, 66560>>>(w_qkvdw);
    k_attn_fin<<<BATCH * HEADS, CH * 32>>>(temperature, rescale);
    k_w2<<<BATCH * HEADS, CDIM>>>(w_proj);
    k_gemm_mma<<<dim3(HW / BN, 2, BATCH), 256, GEMM_SMEM>>>(
        p_A2, p_V, out, CDIM, 256LL * KTOT, (long long)HW * KB_PHYS, (long long)CDIM * HW);
}